// round 2
// baseline (speedup 1.0000x reference)
#include <cuda_runtime.h>
#include <math.h>

#define NLM  25
#define CC   128
#define NB   16384
#define RB   16
#define RA   15
#define GRES 240      // RB*RA
#define PI_D 3.14159265358979323846264338327950288

// ---------------- device globals (scratch; allowed per harness rules) ----------------
__device__ double d_gx[RB];
__device__ float  d_wq[RB];
__device__ float  d_Y[NLM * GRES];          // [i][g*15+h]
__device__ float  d_T2[NLM * NLM * NLM];    // T[i][j][k] * w2[l_k]
__device__ float  g_feat[(size_t)NLM * NB * CC];   // [i][b][c], ~210MB

__constant__ int c_lidx[NLM] = {0, 1,1,1, 2,2,2,2,2, 3,3,3,3,3,3,3, 4,4,4,4,4,4,4,4,4};

// ---------------- init 1: Gauss-Legendre nodes/weights + real SH table Y ----------------
__global__ void init_Y_kernel() {
    __shared__ double sx[RB];
    int t = threadIdx.x;

    if (t < RB) {
        const int n = RB;
        double x = cos(PI_D * (t + 0.75) / (n + 0.5));
        double p0, p1, dp;
        for (int it = 0; it < 64; it++) {
            p0 = 1.0; p1 = x;
            for (int k = 2; k <= n; k++) {
                double pk = ((2.0 * k - 1.0) * x * p1 - (k - 1.0) * p0) / (double)k;
                p0 = p1; p1 = pk;
            }
            dp = n * (x * p1 - p0) / (x * x - 1.0);
            x -= p1 / dp;
        }
        // recompute derivative at converged x for the weight
        p0 = 1.0; p1 = x;
        for (int k = 2; k <= n; k++) {
            double pk = ((2.0 * k - 1.0) * x * p1 - (k - 1.0) * p0) / (double)k;
            p0 = p1; p1 = pk;
        }
        dp = n * (x * p1 - p0) / (x * x - 1.0);
        double w = 2.0 / ((1.0 - x * x) * dp * dp);
        d_gx[t] = x;
        d_wq[t] = (float)(w * (2.0 * PI_D / (double)RA));
        sx[t] = x;
    }
    __syncthreads();

    if (t < GRES) {
        int g = t / RA, h = t % RA;
        double xx = sx[g];
        double s = sqrt(fmax(0.0, 1.0 - xx * xx));
        double P[5][5];
        P[0][0] = 1.0;
        for (int m = 1; m <= 4; m++) P[m][m] = -(2.0 * m - 1.0) * s * P[m - 1][m - 1];
        for (int m = 0; m <= 3; m++) P[m + 1][m] = (2.0 * m + 1.0) * xx * P[m][m];
        for (int m = 0; m <= 4; m++)
            for (int l = m + 2; l <= 4; l++)
                P[l][m] = ((2.0 * l - 1.0) * xx * P[l - 1][m] - (l + m - 1.0) * P[l - 2][m]) / (double)(l - m);

        double alpha = 2.0 * PI_D * (double)h / (double)RA;
        double fact[9];
        fact[0] = 1.0;
        for (int q = 1; q < 9; q++) fact[q] = fact[q - 1] * q;

        int i = 0;
        for (int l = 0; l <= 4; l++)
            for (int mm = -l; mm <= l; mm++) {
                int am = mm < 0 ? -mm : mm;
                double K = sqrt((2.0 * l + 1.0) / (4.0 * PI_D) * fact[l - am] / fact[l + am]);
                double y;
                if (mm == 0)      y = K * P[l][0];
                else if (mm > 0)  y = sqrt(2.0) * K * P[l][am] * cos(am * alpha);
                else              y = sqrt(2.0) * K * P[l][am] * sin(am * alpha);
                d_Y[i * GRES + t] = (float)y;
                i++;
            }
    }
}

// ---------------- init 2: Gaunt tensor T2[i,j,k] = (sum wq*Yi*Yj*Yk) * w2[l_k] ----------------
__global__ void init_T_kernel(const float* __restrict__ w2) {
    int e = blockIdx.x;              // (i,j) pair, 0..624
    int lane = threadIdx.x;          // 32 threads
    int i = e / NLM, j = e % NLM;
    const float* Yi = d_Y + i * GRES;
    const float* Yj = d_Y + j * GRES;

    float wyy[8];
    int np = 0;
    for (int p = lane; p < GRES; p += 32)
        wyy[np++] = d_wq[p / RA] * Yi[p] * Yj[p];

    for (int k = 0; k < NLM; k++) {
        const float* Yk = d_Y + k * GRES;
        float acc = 0.f;
        int q = 0;
        for (int p = lane; p < GRES; p += 32) acc += wyy[q++] * Yk[p];
        #pragma unroll
        for (int off = 16; off; off >>= 1) acc += __shfl_down_sync(0xffffffffu, acc, off);
        if (lane == 0) d_T2[e * NLM + k] = acc * w2[c_lidx[k]];
    }
}

// ---------------- stage 1: feat[i][b][c] = sum_j M_b[i,j] * f[b,c,j]*w1[c,l_j] ----------------
__global__ void __launch_bounds__(128) feat_kernel(const float* __restrict__ feature,
                                                   const float* __restrict__ sh,
                                                   const float* __restrict__ w1) {
    __shared__ float fs[CC * NLM];   // 3200 floats: raw feature row
    __shared__ float Ms[NLM * NLM];  // 625: M_b
    __shared__ float shs[NLM];

    int b = blockIdx.x, t = threadIdx.x;
    const float* frow = feature + (size_t)b * (CC * NLM);
    #pragma unroll
    for (int q = 0; q < NLM; q++) fs[t + 128 * q] = frow[t + 128 * q];
    if (t < NLM) shs[t] = sh[b * NLM + t];
    __syncthreads();

    for (int e = t; e < NLM * NLM; e += 128) {
        const float* Tr = d_T2 + e * NLM;
        float acc = 0.f;
        #pragma unroll
        for (int k = 0; k < NLM; k++) acc += Tr[k] * shs[k];
        Ms[e] = acc;
    }
    __syncthreads();

    int c = t;
    float w1r[5];
    #pragma unroll
    for (int l = 0; l < 5; l++) w1r[l] = w1[c * 5 + l];

    float img[NLM];
    {
        int off = 0, j = 0;
        #pragma unroll
        for (int l = 0; l <= 4; l++) {
            int dd = 2 * l + 1;
            #pragma unroll
            for (int m = 0; m < dd; m++) { img[j] = fs[off + c * dd + m] * w1r[l]; j++; }
            off += CC * dd;
        }
    }

    float* gp = g_feat + (size_t)b * CC + c;
    #pragma unroll
    for (int i2 = 0; i2 < NLM; i2++) {
        float acc = 0.f;
        #pragma unroll
        for (int j = 0; j < NLM; j++) acc += Ms[i2 * NLM + j] * img[j];
        gp[(size_t)i2 * NB * CC] = acc;
    }
}

// ---------------- stage 2: out GEMMs  out_i = feat_i[16384x128] @ wc[l_i][128x128] ----------------
__global__ void __launch_bounds__(256) out_kernel(const float* __restrict__ wc,
                                                  float* __restrict__ out) {
    int i  = blockIdx.x;         // lm index 0..24
    int bt = blockIdx.y;         // b tile 0..127
    int l  = c_lidx[i];
    int dd = 2 * l + 1, ll = l * l, mi = i - ll;

    const float* A  = g_feat + (size_t)i * NB * CC + (size_t)bt * 128 * CC;  // [128 b][128 c]
    const float* Bw = wc + (size_t)l * CC * CC;                               // [128 c][128 a]

    __shared__ float As[8][128];   // [k][m]  (transposed)
    __shared__ float Bs[8][128];   // [k][n]

    int t  = threadIdx.x;
    int tm = t >> 4, tn = t & 15;  // 16x16 thread grid, 8x8 micro-tile

    float acc[8][8];
    #pragma unroll
    for (int a = 0; a < 8; a++)
        #pragma unroll
        for (int b2 = 0; b2 < 8; b2++) acc[a][b2] = 0.f;

    int arow = t >> 1;           // 0..127
    int akq  = (t & 1) * 4;      // 0 / 4
    int brow = t >> 5;           // 0..7
    int bcol = (t & 31) * 4;     // 0..124

    for (int k0 = 0; k0 < 128; k0 += 8) {
        float4 av = *(const float4*)(A  + arow * 128 + k0 + akq);
        float4 bv = *(const float4*)(Bw + (size_t)(k0 + brow) * 128 + bcol);
        __syncthreads();
        As[akq + 0][arow] = av.x;
        As[akq + 1][arow] = av.y;
        As[akq + 2][arow] = av.z;
        As[akq + 3][arow] = av.w;
        *(float4*)(&Bs[brow][bcol]) = bv;
        __syncthreads();

        #pragma unroll
        for (int kk = 0; kk < 8; kk++) {
            float af[8], bf[8];
            *(float4*)(af)     = *(const float4*)(&As[kk][tm * 8]);
            *(float4*)(af + 4) = *(const float4*)(&As[kk][tm * 8 + 4]);
            *(float4*)(bf)     = *(const float4*)(&Bs[kk][tn * 8]);
            *(float4*)(bf + 4) = *(const float4*)(&Bs[kk][tn * 8 + 4]);
            #pragma unroll
            for (int a = 0; a < 8; a++)
                #pragma unroll
                for (int b2 = 0; b2 < 8; b2++)
                    acc[a][b2] += af[a] * bf[b2];
        }
    }

    // out[b, 128*ll + a*dd + mi]
    #pragma unroll
    for (int a = 0; a < 8; a++) {
        int r = tm * 8 + a;
        float* orow = out + ((size_t)(bt * 128 + r)) * (CC * NLM) + 128 * ll + mi;
        #pragma unroll
        for (int b2 = 0; b2 < 8; b2++) {
            int col_a = tn * 8 + b2;
            orow[col_a * dd] = acc[a][b2];
        }
    }
}

// ---------------- launch ----------------
extern "C" void kernel_launch(void* const* d_in, const int* in_sizes, int n_in,
                              void* d_out, int out_size) {
    const float* feature = (const float*)d_in[0];
    const float* sh      = (const float*)d_in[1];
    const float* w1      = (const float*)d_in[2];
    const float* w2      = (const float*)d_in[3];
    const float* wc      = (const float*)d_in[4];
    float* out = (float*)d_out;

    init_Y_kernel<<<1, 256>>>();
    init_T_kernel<<<NLM * NLM, 32>>>(w2);
    feat_kernel<<<NB, 128>>>(feature, sh, w1);
    out_kernel<<<dim3(NLM, NB / 128), 256>>>(wc, out);
}

// round 3
// speedup vs baseline: 1.6282x; 1.6282x over previous
#include <cuda_runtime.h>
#include <math.h>

#define NLM  25
#define CC   128
#define NB   16384
#define RB   16
#define RA   15
#define GRES 240      // RB*RA
#define PI_D 3.14159265358979323846264338327950288
typedef unsigned long long ull;

// ---------------- device globals ----------------
__device__ float  d_wq[RB];
__device__ float  d_Y[NLM * GRES];             // [i][g*15+h]
__device__ float  d_T2[NLM * NLM * NLM];       // k-major: [k][e], e = i*25+j  (w2 folded in)
__device__ float  g_feat[(size_t)NLM * NB * CC];   // [i][b][c]

__constant__ int c_lidx[NLM] = {0, 1,1,1, 2,2,2,2,2, 3,3,3,3,3,3,3, 4,4,4,4,4,4,4,4,4};

// Gauss-Legendre 16-point (positive half); matches numpy leggauss to ~1e-16
__constant__ double c_glx[8] = {
    0.09501250983763744, 0.28160355077925891, 0.45801677765722739, 0.61787624440264375,
    0.75540440835500303, 0.86563120238783174, 0.94457502307323258, 0.98940093499164993 };
__constant__ double c_glw[8] = {
    0.18945061045506850, 0.18260341504492359, 0.16915651939500254, 0.14959598881657673,
    0.12462897125553387, 0.09515851168249278, 0.06225352393864789, 0.02715245941175409 };

// ---------------- f32x2 helpers ----------------
__device__ __forceinline__ ull pk(float lo, float hi) {
    ull r; asm("mov.b64 %0, {%1, %2};" : "=l"(r) : "f"(lo), "f"(hi)); return r;
}
__device__ __forceinline__ void upk(ull v, float &lo, float &hi) {
    asm("mov.b64 {%0, %1}, %2;" : "=f"(lo), "=f"(hi) : "l"(v));
}
__device__ __forceinline__ void fma2(ull &d, ull a, ull b) {
    asm("fma.rn.f32x2 %0, %1, %2, %0;" : "+l"(d) : "l"(a), "l"(b));
}

// ---------------- init 1: Y table + quadrature weights ----------------
__global__ void init_Y_kernel() {
    int t = threadIdx.x;
    if (t < RB) {
        int q = t & 7;
        d_wq[t] = (float)(c_glw[q] * (2.0 * PI_D / (double)RA));
    }
    if (t < GRES) {
        int g = t / RA, h = t % RA;
        double xx = (g < 8) ? c_glx[g] : -c_glx[g - 8];
        double s = sqrt(fmax(0.0, 1.0 - xx * xx));
        double P[5][5];
        P[0][0] = 1.0;
        for (int m = 1; m <= 4; m++) P[m][m] = -(2.0 * m - 1.0) * s * P[m - 1][m - 1];
        for (int m = 0; m <= 3; m++) P[m + 1][m] = (2.0 * m + 1.0) * xx * P[m][m];
        for (int m = 0; m <= 4; m++)
            for (int l = m + 2; l <= 4; l++)
                P[l][m] = ((2.0 * l - 1.0) * xx * P[l - 1][m] - (l + m - 1.0) * P[l - 2][m]) / (double)(l - m);

        double alpha = 2.0 * PI_D * (double)h / (double)RA;
        double fact[9];
        fact[0] = 1.0;
        for (int q2 = 1; q2 < 9; q2++) fact[q2] = fact[q2 - 1] * q2;

        int i = 0;
        for (int l = 0; l <= 4; l++)
            for (int mm = -l; mm <= l; mm++) {
                int am = mm < 0 ? -mm : mm;
                double K = sqrt((2.0 * l + 1.0) / (4.0 * PI_D) * fact[l - am] / fact[l + am]);
                double y;
                if (mm == 0)      y = K * P[l][0];
                else if (mm > 0)  y = sqrt(2.0) * K * P[l][am] * cos(am * alpha);
                else              y = sqrt(2.0) * K * P[l][am] * sin(am * alpha);
                d_Y[i * GRES + t] = (float)y;
                i++;
            }
    }
}

// ---------------- init 2: T2[k][e] = (sum wq*Yi*Yj*Yk) * w2[l_k], k-major layout ----------------
__global__ void init_T_kernel(const float* __restrict__ w2) {
    int e = blockIdx.x;              // (i,j), 0..624
    int lane = threadIdx.x;          // 32
    int i = e / NLM, j = e % NLM;
    const float* Yi = d_Y + i * GRES;
    const float* Yj = d_Y + j * GRES;

    float wyy[8];
    int np = 0;
    for (int p = lane; p < GRES; p += 32)
        wyy[np++] = d_wq[p / RA] * Yi[p] * Yj[p];

    for (int k = 0; k < NLM; k++) {
        const float* Yk = d_Y + k * GRES;
        float acc = 0.f;
        int q = 0;
        for (int p = lane; p < GRES; p += 32) acc += wyy[q++] * Yk[p];
        #pragma unroll
        for (int off = 16; off; off >>= 1) acc += __shfl_down_sync(0xffffffffu, acc, off);
        if (lane == 0) d_T2[k * (NLM * NLM) + e] = acc * w2[c_lidx[k]];
    }
}

// ---------------- stage 1: feat[i][b][c] = sum_j M_b[i,j] * image[b,c,j] ----------------
// 64 threads per CTA, 2 channels per thread (c and c+64), f32x2 packed over j-pairs.
__global__ void __launch_bounds__(64) feat_kernel(const float* __restrict__ feature,
                                                  const float* __restrict__ sh,
                                                  const float* __restrict__ w1) {
    __shared__ float fs[CC * NLM];      // 3200 floats
    __shared__ float Ms[NLM * 26];      // padded row stride 26 (8B-aligned pairs)
    __shared__ float shs[NLM];

    int b = blockIdx.x, t = threadIdx.x;
    const float* frow = feature + (size_t)b * (CC * NLM);
    for (int q = t; q < CC * NLM / 4; q += 64)
        ((float4*)fs)[q] = ((const float4*)frow)[q];
    if (t < NLM) shs[t] = sh[b * NLM + t];
    __syncthreads();

    // M build: coalesced LDG from k-major T2 (lanes read consecutive e)
    for (int e = t; e < NLM * NLM; e += 64) {
        float acc = 0.f;
        #pragma unroll
        for (int k = 0; k < NLM; k++) acc += d_T2[k * (NLM * NLM) + e] * shs[k];
        Ms[(e / NLM) * 26 + (e % NLM)] = acc;
    }
    __syncthreads();

    int c0 = t, c1 = t + 64;

    float img0[NLM], img1[NLM];
    {
        float w1a[5], w1b[5];
        #pragma unroll
        for (int l = 0; l < 5; l++) { w1a[l] = w1[c0 * 5 + l]; w1b[l] = w1[c1 * 5 + l]; }
        int off = 0, j = 0;
        #pragma unroll
        for (int l = 0; l <= 4; l++) {
            int dd = 2 * l + 1;
            #pragma unroll
            for (int m = 0; m < dd; m++) {
                img0[j] = fs[off + c0 * dd + m] * w1a[l];
                img1[j] = fs[off + c1 * dd + m] * w1b[l];
                j++;
            }
            off += CC * dd;
        }
    }

    ull ip0[12], ip1[12];
    #pragma unroll
    for (int jp = 0; jp < 12; jp++) {
        ip0[jp] = pk(img0[2 * jp], img0[2 * jp + 1]);
        ip1[jp] = pk(img1[2 * jp], img1[2 * jp + 1]);
    }

    float* gp = g_feat + (size_t)b * CC;
    #pragma unroll
    for (int i2 = 0; i2 < NLM; i2++) {
        ull a0 = 0ULL, a1 = 0ULL;
        const float* Mr = Ms + i2 * 26;
        #pragma unroll
        for (int jp = 0; jp < 12; jp++) {
            ull mp = *(const ull*)(Mr + 2 * jp);   // (Ms[2jp], Ms[2jp+1])
            fma2(a0, mp, ip0[jp]);
            fma2(a1, mp, ip1[jp]);
        }
        float l0, h0, l1, h1;
        upk(a0, l0, h0); upk(a1, l1, h1);
        float m24 = Mr[24];
        float s0 = l0 + h0 + m24 * img0[24];
        float s1 = l1 + h1 + m24 * img1[24];
        gp[(size_t)i2 * NB * CC + c0] = s0;
        gp[(size_t)i2 * NB * CC + c1] = s1;
    }
}

// ---------------- stage 2: out GEMMs with f32x2, double-buffered smem ----------------
#define KT 16
__global__ void __launch_bounds__(256, 2) out_kernel(const float* __restrict__ wc,
                                                     float* __restrict__ out) {
    int i  = blockIdx.x;         // lm index
    int bt = blockIdx.y;         // b tile
    int l  = c_lidx[i];
    int dd = 2 * l + 1, ll = l * l, mi = i - ll;

    const float* A  = g_feat + (size_t)i * NB * CC + (size_t)bt * 128 * CC;  // [128 b][128 c]
    const float* Bw = wc + (size_t)l * CC * CC;                               // [128 c][128 a]

    __shared__ float As[2][KT][128];   // [k][m]
    __shared__ float Bs[2][KT][128];   // [k][n]

    int t  = threadIdx.x;
    int tm = t >> 4, tn = t & 15;

    int arow = t >> 1;             // 0..127
    int akq  = (t & 1) * 8;        // 0 / 8
    int brow = t >> 5;             // 0..7
    int bcol = (t & 31) * 4;

    ull acc[4][8];
    #pragma unroll
    for (int mp = 0; mp < 4; mp++)
        #pragma unroll
        for (int nn = 0; nn < 8; nn++) acc[mp][nn] = 0ULL;

    // prologue: tile 0 -> buf 0
    float4 ra0 = *(const float4*)(A + arow * 128 + akq);
    float4 ra1 = *(const float4*)(A + arow * 128 + akq + 4);
    float4 rb0 = *(const float4*)(Bw + (size_t)brow * 128 + bcol);
    float4 rb1 = *(const float4*)(Bw + (size_t)(brow + 8) * 128 + bcol);
    As[0][akq + 0][arow] = ra0.x; As[0][akq + 1][arow] = ra0.y;
    As[0][akq + 2][arow] = ra0.z; As[0][akq + 3][arow] = ra0.w;
    As[0][akq + 4][arow] = ra1.x; As[0][akq + 5][arow] = ra1.y;
    As[0][akq + 6][arow] = ra1.z; As[0][akq + 7][arow] = ra1.w;
    *(float4*)(&Bs[0][brow][bcol])     = rb0;
    *(float4*)(&Bs[0][brow + 8][bcol]) = rb1;
    __syncthreads();

    #pragma unroll
    for (int tile = 0; tile < 8; tile++) {
        int buf = tile & 1;
        if (tile < 7) {
            int k0n = (tile + 1) * KT;
            ra0 = *(const float4*)(A + arow * 128 + k0n + akq);
            ra1 = *(const float4*)(A + arow * 128 + k0n + akq + 4);
            rb0 = *(const float4*)(Bw + (size_t)(k0n + brow) * 128 + bcol);
            rb1 = *(const float4*)(Bw + (size_t)(k0n + brow + 8) * 128 + bcol);
        }

        #pragma unroll
        for (int kk = 0; kk < KT; kk++) {
            ulonglong2 av0 = *(const ulonglong2*)(&As[buf][kk][tm * 8]);
            ulonglong2 av1 = *(const ulonglong2*)(&As[buf][kk][tm * 8 + 4]);
            float4 bv0 = *(const float4*)(&Bs[buf][kk][tn * 8]);
            float4 bv1 = *(const float4*)(&Bs[buf][kk][tn * 8 + 4]);
            ull am[4] = { av0.x, av0.y, av1.x, av1.y };
            ull bp[8];
            bp[0] = pk(bv0.x, bv0.x); bp[1] = pk(bv0.y, bv0.y);
            bp[2] = pk(bv0.z, bv0.z); bp[3] = pk(bv0.w, bv0.w);
            bp[4] = pk(bv1.x, bv1.x); bp[5] = pk(bv1.y, bv1.y);
            bp[6] = pk(bv1.z, bv1.z); bp[7] = pk(bv1.w, bv1.w);
            #pragma unroll
            for (int mp = 0; mp < 4; mp++)
                #pragma unroll
                for (int nn = 0; nn < 8; nn++)
                    fma2(acc[mp][nn], am[mp], bp[nn]);
        }

        if (tile < 7) {
            int nb2 = buf ^ 1;
            As[nb2][akq + 0][arow] = ra0.x; As[nb2][akq + 1][arow] = ra0.y;
            As[nb2][akq + 2][arow] = ra0.z; As[nb2][akq + 3][arow] = ra0.w;
            As[nb2][akq + 4][arow] = ra1.x; As[nb2][akq + 5][arow] = ra1.y;
            As[nb2][akq + 6][arow] = ra1.z; As[nb2][akq + 7][arow] = ra1.w;
            *(float4*)(&Bs[nb2][brow][bcol])     = rb0;
            *(float4*)(&Bs[nb2][brow + 8][bcol]) = rb1;
            __syncthreads();
        }
    }

    // epilogue: out[b, 128*ll + a*dd + mi]
    size_t obase = (size_t)(bt * 128 + tm * 8) * (CC * NLM) + 128 * ll + mi;
    #pragma unroll
    for (int mp = 0; mp < 4; mp++) {
        #pragma unroll
        for (int nn = 0; nn < 8; nn++) {
            float lo, hi;
            upk(acc[mp][nn], lo, hi);
            int col = tn * 8 + nn;
            out[obase + (size_t)(2 * mp) * (CC * NLM) + col * dd]     = lo;
            out[obase + (size_t)(2 * mp + 1) * (CC * NLM) + col * dd] = hi;
        }
    }
}

// ---------------- launch ----------------
extern "C" void kernel_launch(void* const* d_in, const int* in_sizes, int n_in,
                              void* d_out, int out_size) {
    const float* feature = (const float*)d_in[0];
    const float* sh      = (const float*)d_in[1];
    const float* w1      = (const float*)d_in[2];
    const float* w2      = (const float*)d_in[3];
    const float* wc      = (const float*)d_in[4];
    float* out = (float*)d_out;

    init_Y_kernel<<<1, 256>>>();
    init_T_kernel<<<NLM * NLM, 32>>>(w2);
    feat_kernel<<<NB, 64>>>(feature, sh, w1);
    out_kernel<<<dim3(NLM, NB / 128), 256>>>(wc, out);
}

// round 7
// speedup vs baseline: 1.8309x; 1.1245x over previous
#include <cuda_runtime.h>
#include <cuda_bf16.h>
#include <math.h>
#include <stdint.h>

#define NLM  25
#define CC   128
#define NB   16384
#define RB   16
#define RA   15
#define GRES 240
#define PI_D 3.14159265358979323846264338327950288
typedef unsigned long long ull;

// ---------------- device globals ----------------
__device__ float  d_wq[RB];
__device__ float  d_Y[NLM * GRES];
__device__ float  d_T2[NLM * NLM * NLM];                 // k-major: [k][e], e=i*25+j (w2 folded)
__device__ float  d_M[(size_t)NB * 656];                 // per-b M, row stride 656, col = i*26+j
__device__ __nv_bfloat16 g_fh[(size_t)NLM * NB * CC];    // feat hi  [i][b][c]
__device__ __nv_bfloat16 g_fl[(size_t)NLM * NB * CC];    // feat lo

__constant__ int c_lidx[NLM] = {0, 1,1,1, 2,2,2,2,2, 3,3,3,3,3,3,3, 4,4,4,4,4,4,4,4,4};

__constant__ double c_glx[8] = {
    0.09501250983763744, 0.28160355077925891, 0.45801677765722739, 0.61787624440264375,
    0.75540440835500303, 0.86563120238783174, 0.94457502307323258, 0.98940093499164993 };
__constant__ double c_glw[8] = {
    0.18945061045506850, 0.18260341504492359, 0.16915651939500254, 0.14959598881657673,
    0.12462897125553387, 0.09515851168249278, 0.06225352393864789, 0.02715245941175409 };

// ---------------- helpers ----------------
__device__ __forceinline__ ull pk(float lo, float hi) {
    ull r; asm("mov.b64 %0, {%1, %2};" : "=l"(r) : "f"(lo), "f"(hi)); return r;
}
__device__ __forceinline__ void upk(ull v, float &lo, float &hi) {
    asm("mov.b64 {%0, %1}, %2;" : "=f"(lo), "=f"(hi) : "l"(v));
}
__device__ __forceinline__ void fma2(ull &d, ull a, ull b) {
    asm("fma.rn.f32x2 %0, %1, %2, %0;" : "+l"(d) : "l"(a), "l"(b));
}
__device__ __forceinline__ uint32_t smem_u32(const void* p) {
    uint32_t a;
    asm("{ .reg .u64 t; cvta.to.shared.u64 t, %1; cvt.u32.u64 %0, t; }" : "=r"(a) : "l"(p));
    return a;
}
__device__ __forceinline__ void cpa16(uint32_t dst, const void* src) {
    asm volatile("cp.async.cg.shared.global [%0], [%1], 16;" :: "r"(dst), "l"(src) : "memory");
}
#define CP_COMMIT() asm volatile("cp.async.commit_group;" ::: "memory")
#define CP_WAIT(n)  asm volatile("cp.async.wait_group %0;" :: "n"(n) : "memory")

__device__ __forceinline__ void ldsm4(uint32_t* r, uint32_t addr) {
    asm volatile("ldmatrix.sync.aligned.m8n8.x4.shared.b16 {%0,%1,%2,%3}, [%4];"
        : "=r"(r[0]), "=r"(r[1]), "=r"(r[2]), "=r"(r[3]) : "r"(addr));
}
__device__ __forceinline__ void mma16816(float* d, const uint32_t* a, const uint32_t* b) {
    asm volatile("mma.sync.aligned.m16n8k16.row.col.f32.bf16.bf16.f32 "
        "{%0,%1,%2,%3}, {%4,%5,%6,%7}, {%8,%9}, {%0,%1,%2,%3};"
        : "+f"(d[0]), "+f"(d[1]), "+f"(d[2]), "+f"(d[3])
        : "r"(a[0]), "r"(a[1]), "r"(a[2]), "r"(a[3]), "r"(b[0]), "r"(b[1]));
}

// ---------------- init 1: Y table + quadrature weights ----------------
__global__ void init_Y_kernel() {
    int t = threadIdx.x;
    if (t < RB) d_wq[t] = (float)(c_glw[t & 7] * (2.0 * PI_D / (double)RA));
    if (t < GRES) {
        int g = t / RA, h = t % RA;
        double xx = (g < 8) ? c_glx[g] : -c_glx[g - 8];
        double s = sqrt(fmax(0.0, 1.0 - xx * xx));
        double P[5][5];
        P[0][0] = 1.0;
        for (int m = 1; m <= 4; m++) P[m][m] = -(2.0 * m - 1.0) * s * P[m - 1][m - 1];
        for (int m = 0; m <= 3; m++) P[m + 1][m] = (2.0 * m + 1.0) * xx * P[m][m];
        for (int m = 0; m <= 4; m++)
            for (int l = m + 2; l <= 4; l++)
                P[l][m] = ((2.0 * l - 1.0) * xx * P[l - 1][m] - (l + m - 1.0) * P[l - 2][m]) / (double)(l - m);
        double alpha = 2.0 * PI_D * (double)h / (double)RA;
        double fact[9]; fact[0] = 1.0;
        for (int q = 1; q < 9; q++) fact[q] = fact[q - 1] * q;
        int i = 0;
        for (int l = 0; l <= 4; l++)
            for (int mm = -l; mm <= l; mm++) {
                int am = mm < 0 ? -mm : mm;
                double K = sqrt((2.0 * l + 1.0) / (4.0 * PI_D) * fact[l - am] / fact[l + am]);
                double y;
                if (mm == 0)      y = K * P[l][0];
                else if (mm > 0)  y = sqrt(2.0) * K * P[l][am] * cos(am * alpha);
                else              y = sqrt(2.0) * K * P[l][am] * sin(am * alpha);
                d_Y[i * GRES + t] = (float)y;
                i++;
            }
    }
}

// ---------------- init 2: T2[k][e] ----------------
__global__ void init_T_kernel(const float* __restrict__ w2) {
    int e = blockIdx.x, lane = threadIdx.x;
    int i = e / NLM, j = e % NLM;
    const float* Yi = d_Y + i * GRES;
    const float* Yj = d_Y + j * GRES;
    float wyy[8]; int np = 0;
    for (int p = lane; p < GRES; p += 32) wyy[np++] = d_wq[p / RA] * Yi[p] * Yj[p];
    for (int k = 0; k < NLM; k++) {
        const float* Yk = d_Y + k * GRES;
        float acc = 0.f; int q = 0;
        for (int p = lane; p < GRES; p += 32) acc += wyy[q++] * Yk[p];
        #pragma unroll
        for (int off = 16; off; off >>= 1) acc += __shfl_down_sync(0xffffffffu, acc, off);
        if (lane == 0) d_T2[k * (NLM * NLM) + e] = acc * w2[c_lidx[k]];
    }
}

// ---------------- stage 0: M[b][i,j] = sum_k T2[k][e]*sh[b][k], T2 in smem ----------------
__global__ void __launch_bounds__(320) msolve_kernel(const float* __restrict__ sh) {
    extern __shared__ float dsm[];
    float* T2s = dsm;                    // [k*640 + e]
    ull* shp = (ull*)(dsm + 25 * 640);   // [k*32 + bp]
    int t = threadIdx.x;
    int b0 = blockIdx.x * 64;

    for (int q = t; q < 25 * 640; q += 320) {
        int k = q / 640, e = q % 640;
        T2s[q] = (e < 625) ? d_T2[k * 625 + e] : 0.f;
    }
    for (int q = t; q < 25 * 32; q += 320) {
        int k = q >> 5, bp = q & 31;
        shp[q] = pk(sh[(size_t)(b0 + 2 * bp) * 25 + k], sh[(size_t)(b0 + 2 * bp + 1) * 25 + k]);
    }
    __syncthreads();

    int e0 = t, e1 = t + 320;
    ull t2p0[25], t2p1[25];
    #pragma unroll
    for (int k = 0; k < 25; k++) {
        float v0 = T2s[k * 640 + e0], v1 = T2s[k * 640 + e1];
        t2p0[k] = pk(v0, v0); t2p1[k] = pk(v1, v1);
    }
    int col0 = (e0 / 25) * 26 + e0 % 25;
    int col1 = (e1 / 25) * 26 + e1 % 25;
    bool v1ok = e1 < 625;

    for (int bp = 0; bp < 32; bp++) {
        ull a0 = 0ULL, a1 = 0ULL;
        #pragma unroll
        for (int k = 0; k < 25; k++) {
            ull sp = shp[k * 32 + bp];
            fma2(a0, t2p0[k], sp);
            fma2(a1, t2p1[k], sp);
        }
        float x0, x1, y0, y1;
        upk(a0, x0, x1); upk(a1, y0, y1);
        size_t r0 = (size_t)(b0 + 2 * bp) * 656, r1 = r0 + 656;
        d_M[r0 + col0] = x0; d_M[r1 + col0] = x1;
        if (v1ok) { d_M[r0 + col1] = y0; d_M[r1 + col1] = y1; }
    }
}

// ---------------- stage 1: feat (bf16 hi/lo) ----------------
__global__ void __launch_bounds__(128) feat_kernel(const float* __restrict__ feature,
                                                   const float* __restrict__ w1) {
    __shared__ float fs[CC * NLM];
    __shared__ __align__(16) float Ms[656];
    int b = blockIdx.x, t = threadIdx.x;

    const float4* f4 = (const float4*)(feature + (size_t)b * (CC * NLM));
    for (int q = t; q < CC * NLM / 4; q += 128) ((float4*)fs)[q] = f4[q];
    const float4* m4 = (const float4*)(d_M + (size_t)b * 656);
    for (int q = t; q < 164; q += 128) ((float4*)Ms)[q] = m4[q];
    __syncthreads();

    int c = t;
    float w1r[5];
    #pragma unroll
    for (int l = 0; l < 5; l++) w1r[l] = w1[c * 5 + l];

    float img[NLM];
    {
        int off = 0, j = 0;
        #pragma unroll
        for (int l = 0; l <= 4; l++) {
            int dd = 2 * l + 1;
            #pragma unroll
            for (int m = 0; m < dd; m++) { img[j] = fs[off + c * dd + m] * w1r[l]; j++; }
            off += CC * dd;
        }
    }
    ull ip[12];
    #pragma unroll
    for (int jp = 0; jp < 12; jp++) ip[jp] = pk(img[2 * jp], img[2 * jp + 1]);
    float i24 = img[24];

    size_t bi = (size_t)b * CC + c;
    #pragma unroll
    for (int i2 = 0; i2 < NLM; i2++) {
        const float* Mr = Ms + i2 * 26;
        ull a0 = 0ULL;
        #pragma unroll
        for (int jp = 0; jp < 12; jp++) fma2(a0, *(const ull*)(Mr + 2 * jp), ip[jp]);
        float lo, hi; upk(a0, lo, hi);
        float f = lo + hi + Mr[24] * i24;
        __nv_bfloat16 h  = __float2bfloat16(f);
        __nv_bfloat16 lw = __float2bfloat16(f - __bfloat162float(h));
        size_t idx = (size_t)i2 * NB * CC + bi;
        g_fh[idx] = h;
        g_fl[idx] = lw;
    }
}

// ---------------- stage 2: warp-level HMMA GEMM, bf16-split 3-pass ----------------
// smem (1024-aligned base): Ah 32K | Al 32K | Bh 32K | Bl 32K
// Layout for all tiles: [row][k] bf16, row stride 256B, 16B chunks XOR-swizzled:
//   addr(row, chunk) = base + row*256 + ((chunk ^ (row&7)) << 4)
#define SA_H 0
#define SA_L 32768
#define SB_H 65536
#define SB_L 98304

__global__ void __launch_bounds__(256) out_gemm(const float* __restrict__ wc,
                                                float* __restrict__ out) {
    extern __shared__ char raw[];
    uint32_t sb = smem_u32(raw);
    uint32_t base = (sb + 1023) & ~1023u;
    char* cb = raw + (base - sb);

    int i  = blockIdx.x;           // lm index
    int bt = blockIdx.y;           // b tile (128 rows)
    int l  = c_lidx[i];
    int dd = 2 * l + 1, ll = l * l, mi = i - ll;
    int t = threadIdx.x, wid = t >> 5, lane = t & 31;
    int wr = wid >> 2, wcid = wid & 3;   // warp tile: rows wr*64+..., cols wcid*32+...

    // ---- A hi/lo via cp.async (two groups) ----
    size_t arowbase = ((size_t)i * NB + (size_t)bt * 128) * CC;
    {
        const char* srcH = (const char*)(g_fh + arowbase);
        for (int q = t; q < 2048; q += 256) {
            int r = q >> 4, c16 = q & 15;
            cpa16(base + SA_H + r * 256 + ((c16 ^ (r & 7)) << 4), srcH + q * 16);
        }
        CP_COMMIT();
        const char* srcL = (const char*)(g_fl + arowbase);
        for (int q = t; q < 2048; q += 256) {
            int r = q >> 4, c16 = q & 15;
            cpa16(base + SA_L + r * 256 + ((c16 ^ (r & 7)) << 4), srcL + q * 16);
        }
        CP_COMMIT();
    }

    // ---- B tiles: wc[l]^T hi/lo (LDG fp32 + convert + STS), overlaps A cp.async ----
    {
        const float* wl = wc + (size_t)l * (CC * CC);
        for (int q = t; q < CC * CC; q += 256) {
            int c = q >> 7, a = q & 127;       // B row = a (n), col = c (k)
            float w = wl[q];
            __nv_bfloat16 h  = __float2bfloat16(w);
            __nv_bfloat16 lo = __float2bfloat16(w - __bfloat162float(h));
            uint32_t off = (uint32_t)(a * 256 + (((c >> 3) ^ (a & 7)) << 4) + (c & 7) * 2);
            *(__nv_bfloat16*)(cb + SB_H + off) = h;
            *(__nv_bfloat16*)(cb + SB_L + off) = lo;
        }
    }

    // ---- fragment address precompute ----
    int ra = ((lane >> 3) & 1) * 8 + (lane & 7);     // A ldmatrix row-in-16
    int rb = ((lane >> 4) & 1) * 8 + (lane & 7);     // B ldmatrix row-in-16
    int rsw = lane & 7;
    int ckA_off = (lane >> 4) & 1;                   // k-chunk offset per lane (A)
    int ckB_off = (lane >> 3) & 1;                   // (B)
    uint32_t arow[4], brow[2];
    #pragma unroll
    for (int mt = 0; mt < 4; mt++) arow[mt] = (uint32_t)((wr * 64 + mt * 16 + ra) * 256);
    #pragma unroll
    for (int pt = 0; pt < 2; pt++) brow[pt] = (uint32_t)((wcid * 32 + pt * 16 + rb) * 256);

    float acc[4][4][4];
    #pragma unroll
    for (int mt = 0; mt < 4; mt++)
        #pragma unroll
        for (int nt = 0; nt < 4; nt++)
            #pragma unroll
            for (int e = 0; e < 4; e++) acc[mt][nt][e] = 0.f;

    // ---- compute: pass 0 = Ah*Bh, pass 1 = Ah*Bl, pass 2 = Al*Bh ----
    CP_WAIT(1);            // Ah resident
    __syncthreads();       // Ah + B STS visible to all warps

    #pragma unroll
    for (int pass = 0; pass < 3; pass++) {
        if (pass == 2) { CP_WAIT(0); __syncthreads(); }   // Al resident
        uint32_t abase = base + ((pass == 2) ? SA_L : SA_H);
        uint32_t bbase = base + ((pass == 1) ? SB_L : SB_H);
        #pragma unroll
        for (int s = 0; s < 8; s++) {
            uint32_t swA = (uint32_t)(((2 * s + ckA_off) ^ rsw) << 4);
            uint32_t swB = (uint32_t)(((2 * s + ckB_off) ^ rsw) << 4);
            uint32_t af[4][4], bf[2][4];
            #pragma unroll
            for (int mt = 0; mt < 4; mt++) ldsm4(af[mt], abase + arow[mt] + swA);
            #pragma unroll
            for (int pt = 0; pt < 2; pt++) ldsm4(bf[pt], bbase + brow[pt] + swB);
            #pragma unroll
            for (int mt = 0; mt < 4; mt++) {
                #pragma unroll
                for (int nt = 0; nt < 4; nt++)
                    mma16816(acc[mt][nt], af[mt], &bf[nt >> 1][(nt & 1) * 2]);
            }
        }
    }

    // ---- epilogue: out[b, 128*ll + a*dd + mi] ----
    #pragma unroll
    for (int mt = 0; mt < 4; mt++) {
        int r0 = bt * 128 + wr * 64 + mt * 16 + (lane >> 2);
        float* o0 = out + (size_t)r0 * (CC * NLM) + 128 * ll + mi;
        float* o1 = o0 + 8 * (size_t)(CC * NLM);
        #pragma unroll
        for (int nt = 0; nt < 4; nt++) {
            int col = wcid * 32 + nt * 8 + (lane & 3) * 2;
            o0[col * dd]       = acc[mt][nt][0];
            o0[(col + 1) * dd] = acc[mt][nt][1];
            o1[col * dd]       = acc[mt][nt][2];
            o1[(col + 1) * dd] = acc[mt][nt][3];
        }
    }
}

// ---------------- launch ----------------
extern "C" void kernel_launch(void* const* d_in, const int* in_sizes, int n_in,
                              void* d_out, int out_size) {
    const float* feature = (const float*)d_in[0];
    const float* sh      = (const float*)d_in[1];
    const float* w1      = (const float*)d_in[2];
    const float* w2      = (const float*)d_in[3];
    const float* wc      = (const float*)d_in[4];
    float* out = (float*)d_out;

    const int MS_SMEM  = 25 * 640 * 4 + 25 * 32 * 8;   // 70400
    const int OUT_SMEM = 131072 + 1024;
    cudaFuncSetAttribute(msolve_kernel, cudaFuncAttributeMaxDynamicSharedMemorySize, MS_SMEM);
    cudaFuncSetAttribute(out_gemm,      cudaFuncAttributeMaxDynamicSharedMemorySize, OUT_SMEM);

    init_Y_kernel<<<1, 256>>>();
    init_T_kernel<<<NLM * NLM, 32>>>(w2);
    msolve_kernel<<<NB / 64, 320, MS_SMEM>>>(sh);
    feat_kernel<<<NB, 128>>>(feature, w1);
    out_gemm<<<dim3(NLM, NB / 128), 256, OUT_SMEM>>>(wc, out);
}